// round 5
// baseline (speedup 1.0000x reference)
#include <cuda_runtime.h>
#include <cstdint>

// Problem constants
#define B_DIM   8192
#define IN_DIM  256
#define OUT_DIM 256
#define MV      8

// Tiling
#define MT      64           // b rows per CTA (32 b-pairs)
#define NBP     32
#define IT      64           // i per CTA
#define KJ      8            // j per chunk
#define NCH     (IN_DIM / KJ)   // 32
#define XPAD    34           // 32 bpairs + pad (rows 16B-aligned)

typedef unsigned long long u64;

struct __align__(16) Smem {
    u64 X[2][KJ][5][XPAD];   // comps: x0,x1,x2,x4,-x2 as {b even, b odd} pairs
    u64 W[2][3][KJ][IT];     // w0,w1,w2 duplicated {w,w}
};

__device__ __forceinline__ u64 pack2(float lo, float hi) {
    u64 r; asm("mov.b64 %0, {%1, %2};" : "=l"(r) : "f"(lo), "f"(hi)); return r;
}
__device__ __forceinline__ u64 fma2(u64 a, u64 b, u64 c) {
    u64 d; asm("fma.rn.f32x2 %0, %1, %2, %3;" : "=l"(d) : "l"(a), "l"(b), "l"(c)); return d;
}
__device__ __forceinline__ void unpack2(u64 v, float& lo, float& hi) {
    asm("mov.b64 {%0, %1}, %2;" : "=f"(lo), "=f"(hi) : "l"(v));
}

// y[b,i,0] = bias[i,0] + sum_j x0*w0 + x1*w1 + x2*w2
// y[b,i,4] = bias[i,4] + sum_j x1*w2 - x2*w1 + x4*w0
__global__ void __launch_bounds__(256, 3)
ga_mv_kernel(const float* __restrict__ x,
             const float* __restrict__ w,
             const float* __restrict__ bias,
             float* __restrict__ out)
{
    extern __shared__ char smraw[];
    Smem* sm = (Smem*)smraw;

    const int tid   = threadIdx.x;
    const int tx    = tid & 15;        // i = tx + 16q
    const int ty    = tid >> 4;        // bp0 = ty*2
    const int bp0   = ty * 2;
    const int bBase = blockIdx.x * MT;
    const int iBase = blockIdx.y * IT;

    // staging mappings
    const int xj  = tid & 7;           // X: j
    const int xbp = tid >> 3;          // X: bp (0..31), one cell/thread
    const int wi  = tid & 63;          // W: i
    const int wjj = tid >> 6;          // W: j (cells wjj, wjj+4)

    // prefetch registers
    float xA[4], xB[4];                // comps {0,1,2,4} of even/odd row
    float wv[2][3];

    u64 a0[2][4], a4[2][4];
    #pragma unroll
    for (int r = 0; r < 2; r++)
        #pragma unroll
        for (int q = 0; q < 4; q++) { a0[r][q] = 0ull; a4[r][q] = 0ull; }

    auto LOAD = [&](int c) {
        const int j0 = c * KJ;
        {
            const float* ra = x + ((size_t)(bBase + 2 * xbp) * IN_DIM + (j0 + xj)) * MV;
            const float* rb = ra + (size_t)IN_DIM * MV;
            float4 a = *(const float4*)ra;
            xA[0] = a.x; xA[1] = a.y; xA[2] = a.z; xA[3] = ra[4];
            float4 b = *(const float4*)rb;
            xB[0] = b.x; xB[1] = b.y; xB[2] = b.z; xB[3] = rb[4];
        }
        #pragma unroll
        for (int t = 0; t < 2; t++) {
            const float* wr = w + ((size_t)(j0 + wjj + 4 * t) * OUT_DIM + (iBase + wi)) * MV;
            float4 q = *(const float4*)wr;
            wv[t][0] = q.x; wv[t][1] = q.y; wv[t][2] = q.z;
        }
    };

    auto STORE = [&](int buf) {
        sm->X[buf][xj][0][xbp] = pack2(xA[0],  xB[0]);
        sm->X[buf][xj][1][xbp] = pack2(xA[1],  xB[1]);
        sm->X[buf][xj][2][xbp] = pack2(xA[2],  xB[2]);
        sm->X[buf][xj][3][xbp] = pack2(xA[3],  xB[3]);
        sm->X[buf][xj][4][xbp] = pack2(-xA[2], -xB[2]);
        #pragma unroll
        for (int t = 0; t < 2; t++) {
            const int jj = wjj + 4 * t;
            sm->W[buf][0][jj][wi] = pack2(wv[t][0], wv[t][0]);
            sm->W[buf][1][jj][wi] = pack2(wv[t][1], wv[t][1]);
            sm->W[buf][2][jj][wi] = pack2(wv[t][2], wv[t][2]);
        }
    };

    LOAD(0);
    STORE(0);
    __syncthreads();

    for (int c = 0; c < NCH; c++) {
        const int buf = c & 1;
        if (c + 1 < NCH) LOAD(c + 1);

        #pragma unroll
        for (int j = 0; j < KJ; j++) {
            // X: both bpairs per comp in one LDS.128 (bp0 even -> 16B aligned)
            ulonglong2 v0 = *(const ulonglong2*)&sm->X[buf][j][0][bp0];
            ulonglong2 v1 = *(const ulonglong2*)&sm->X[buf][j][1][bp0];
            ulonglong2 v2 = *(const ulonglong2*)&sm->X[buf][j][2][bp0];
            ulonglong2 v3 = *(const ulonglong2*)&sm->X[buf][j][3][bp0];
            ulonglong2 v4 = *(const ulonglong2*)&sm->X[buf][j][4][bp0];
            #pragma unroll
            for (int qh = 0; qh < 2; qh++) {
                u64 W0[2], W1[2], W2[2];
                #pragma unroll
                for (int s = 0; s < 2; s++) {
                    const int q = 2 * qh + s;
                    W0[s] = sm->W[buf][0][j][tx + 16 * q];
                    W1[s] = sm->W[buf][1][j][tx + 16 * q];
                    W2[s] = sm->W[buf][2][j][tx + 16 * q];
                }
                #pragma unroll
                for (int r = 0; r < 2; r++) {
                    const u64 x0  = r ? v0.y : v0.x;
                    const u64 x1  = r ? v1.y : v1.x;
                    const u64 x2  = r ? v2.y : v2.x;
                    const u64 x4  = r ? v3.y : v3.x;
                    const u64 x2n = r ? v4.y : v4.x;
                    #pragma unroll
                    for (int s = 0; s < 2; s++) {
                        const int q = 2 * qh + s;
                        a0[r][q] = fma2(x0,  W0[s], a0[r][q]);
                        a0[r][q] = fma2(x1,  W1[s], a0[r][q]);
                        a0[r][q] = fma2(x2,  W2[s], a0[r][q]);
                        a4[r][q] = fma2(x1,  W2[s], a4[r][q]);
                        a4[r][q] = fma2(x2n, W1[s], a4[r][q]);
                        a4[r][q] = fma2(x4,  W0[s], a4[r][q]);
                    }
                }
            }
        }

        if (c + 1 < NCH) STORE((c + 1) & 1);
        __syncthreads();
    }

    // ---- epilogue: bias + c0/c4 into slots 0 and 4
    #pragma unroll
    for (int q = 0; q < 4; q++) {
        const int ig = iBase + tx + 16 * q;
        float4 blo = *(const float4*)(bias + (size_t)ig * MV);
        float4 bhi = *(const float4*)(bias + (size_t)ig * MV + 4);
        #pragma unroll
        for (int r = 0; r < 2; r++) {
            float c0e, c0o, c4e, c4o;
            unpack2(a0[r][q], c0e, c0o);
            unpack2(a4[r][q], c4e, c4o);
            const int bE = bBase + 2 * (bp0 + r);

            float4 v0 = blo; v0.x += c0e;
            float4 v1 = bhi; v1.x += c4e;
            float4* o = (float4*)(out + ((size_t)bE * OUT_DIM + ig) * MV);
            o[0] = v0; o[1] = v1;

            v0 = blo; v0.x += c0o;
            v1 = bhi; v1.x += c4o;
            o = (float4*)(out + ((size_t)(bE + 1) * OUT_DIM + ig) * MV);
            o[0] = v0; o[1] = v1;
        }
    }
}

extern "C" void kernel_launch(void* const* d_in, const int* in_sizes, int n_in,
                              void* d_out, int out_size)
{
    const float* x    = (const float*)d_in[0];   // (8192, 256, 8)
    const float* w    = (const float*)d_in[1];   // (256, 256, 8)
    const float* bias = (const float*)d_in[2];   // (256, 8)
    float* out        = (float*)d_out;           // (8192, 256, 8)

    static int attr_set = 0;
    if (!attr_set) {
        cudaFuncSetAttribute(ga_mv_kernel, cudaFuncAttributeMaxDynamicSharedMemorySize,
                             (int)sizeof(Smem));
        attr_set = 1;
    }

    dim3 grid(B_DIM / MT, OUT_DIM / IT);         // (128, 4) = 512 CTAs
    ga_mv_kernel<<<grid, 256, sizeof(Smem)>>>(x, w, bias, out);
}

// round 6
// speedup vs baseline: 1.3982x; 1.3982x over previous
#include <cuda_runtime.h>
#include <cstdint>

// Problem constants
#define B_DIM   8192
#define IN_DIM  256
#define OUT_DIM 256
#define MV      8

// Tiling: CTA = 64 b (32 bpairs) x 64 i, 128 threads (tx16 x ty8),
// per thread: 4 bpairs x 4 i  (same amortization as the 200us kernel)
#define MT      64
#define IT      64
#define KJ      8
#define NCH     (IN_DIM / KJ)   // 32
#define XPAD    36              // bp row pad (16B-aligned rows)
#define NTHR    128

typedef unsigned long long u64;

__device__ __forceinline__ u64 pack2(float lo, float hi) {
    u64 r; asm("mov.b64 %0, {%1, %2};" : "=l"(r) : "f"(lo), "f"(hi)); return r;
}
__device__ __forceinline__ u64 fma2(u64 a, u64 b, u64 c) {
    u64 d; asm("fma.rn.f32x2 %0, %1, %2, %3;" : "=l"(d) : "l"(a), "l"(b), "l"(c)); return d;
}
__device__ __forceinline__ void unpack2(u64 v, float& lo, float& hi) {
    asm("mov.b64 {%0, %1}, %2;" : "=f"(lo), "=f"(hi) : "l"(v));
}

// y[b,i,0] = bias[i,0] + sum_j x0*w0 + x1*w1 + x2*w2
// y[b,i,4] = bias[i,4] + sum_j x1*w2 - x2*w1 + x4*w0
__global__ void __launch_bounds__(NTHR, 4)
ga_mv_kernel(const float* __restrict__ x,
             const float* __restrict__ w,
             const float* __restrict__ bias,
             float* __restrict__ out)
{
    // single-buffered tiles: ~24 KB -> 4 CTAs/SM
    __shared__ u64 Xs[KJ][5][XPAD];   // comps x0,x1,x2,x4,-x2 as {b even,b odd}
    __shared__ u64 Ws[3][KJ][IT];     // w0,w1,w2 duplicated {w,w}, i contiguous

    const int tid   = threadIdx.x;
    const int tx    = tid & 15;        // i = tx + 16q, q=0..3
    const int ty    = tid >> 4;        // 0..7
    const int bp0   = ty * 4;          // 4 bpairs per thread
    const int bBase = blockIdx.x * MT;
    const int iBase = blockIdx.y * IT;

    // staging maps
    const int xj  = tid & 7;           // X: j   (2 cells: bp, bp+16)
    const int xbp = tid >> 3;          // X: bp 0..15
    const int wi  = tid & 63;          // W: i   (4 cells: j = 2t + (tid>>6))
    const int wjh = tid >> 6;          // 0..1

    u64 a0[4][4], a4[4][4];
    #pragma unroll
    for (int r = 0; r < 4; r++)
        #pragma unroll
        for (int q = 0; q < 4; q++) { a0[r][q] = 0ull; a4[r][q] = 0ull; }

    for (int c = 0; c < NCH; c++) {
        const int j0 = c * KJ;

        __syncthreads();   // previous compute done before overwrite

        // ---- stage X: 32 bp x 8 j (2 cells/thread)
        #pragma unroll
        for (int t = 0; t < 2; t++) {
            const int bp = xbp + 16 * t;
            const float* ra = x + ((size_t)(bBase + 2 * bp) * IN_DIM + (j0 + xj)) * MV;
            const float* rb = ra + (size_t)IN_DIM * MV;
            float4 a = *(const float4*)ra;
            float  a4v = ra[4];
            float4 b = *(const float4*)rb;
            float  b4v = rb[4];
            Xs[xj][0][bp] = pack2(a.x,  b.x);
            Xs[xj][1][bp] = pack2(a.y,  b.y);
            Xs[xj][2][bp] = pack2(a.z,  b.z);
            Xs[xj][3][bp] = pack2(a4v,  b4v);
            Xs[xj][4][bp] = pack2(-a.z, -b.z);
        }

        // ---- stage W: 8 j x 64 i (4 cells/thread)
        #pragma unroll
        for (int t = 0; t < 4; t++) {
            const int jj = wjh + 2 * t;
            const float* wr = w + ((size_t)(j0 + jj) * OUT_DIM + (iBase + wi)) * MV;
            float4 q = *(const float4*)wr;
            Ws[0][jj][wi] = pack2(q.x, q.x);
            Ws[1][jj][wi] = pack2(q.y, q.y);
            Ws[2][jj][wi] = pack2(q.z, q.z);
        }

        __syncthreads();

        // ---- compute
        #pragma unroll
        for (int j = 0; j < KJ; j++) {
            // X: 5 comps x 2 bpair-pairs, LDS.128 each
            ulonglong2 v0a = *(const ulonglong2*)&Xs[j][0][bp0];
            ulonglong2 v1a = *(const ulonglong2*)&Xs[j][1][bp0];
            ulonglong2 v2a = *(const ulonglong2*)&Xs[j][2][bp0];
            ulonglong2 v3a = *(const ulonglong2*)&Xs[j][3][bp0];
            ulonglong2 v4a = *(const ulonglong2*)&Xs[j][4][bp0];
            ulonglong2 v0b = *(const ulonglong2*)&Xs[j][0][bp0 + 2];
            ulonglong2 v1b = *(const ulonglong2*)&Xs[j][1][bp0 + 2];
            ulonglong2 v2b = *(const ulonglong2*)&Xs[j][2][bp0 + 2];
            ulonglong2 v3b = *(const ulonglong2*)&Xs[j][3][bp0 + 2];
            ulonglong2 v4b = *(const ulonglong2*)&Xs[j][4][bp0 + 2];

            #pragma unroll
            for (int qh = 0; qh < 2; qh++) {
                u64 W0[2], W1[2], W2[2];
                #pragma unroll
                for (int s = 0; s < 2; s++) {
                    const int q = 2 * qh + s;
                    W0[s] = Ws[0][j][tx + 16 * q];
                    W1[s] = Ws[1][j][tx + 16 * q];
                    W2[s] = Ws[2][j][tx + 16 * q];
                }
                #pragma unroll
                for (int r = 0; r < 4; r++) {
                    const u64 x0  = (r & 2) ? ((r & 1) ? v0b.y : v0b.x) : ((r & 1) ? v0a.y : v0a.x);
                    const u64 x1  = (r & 2) ? ((r & 1) ? v1b.y : v1b.x) : ((r & 1) ? v1a.y : v1a.x);
                    const u64 x2  = (r & 2) ? ((r & 1) ? v2b.y : v2b.x) : ((r & 1) ? v2a.y : v2a.x);
                    const u64 x4  = (r & 2) ? ((r & 1) ? v3b.y : v3b.x) : ((r & 1) ? v3a.y : v3a.x);
                    const u64 x2n = (r & 2) ? ((r & 1) ? v4b.y : v4b.x) : ((r & 1) ? v4a.y : v4a.x);
                    #pragma unroll
                    for (int s = 0; s < 2; s++) {
                        const int q = 2 * qh + s;
                        a0[r][q] = fma2(x0,  W0[s], a0[r][q]);
                        a0[r][q] = fma2(x1,  W1[s], a0[r][q]);
                        a0[r][q] = fma2(x2,  W2[s], a0[r][q]);
                        a4[r][q] = fma2(x1,  W2[s], a4[r][q]);
                        a4[r][q] = fma2(x2n, W1[s], a4[r][q]);
                        a4[r][q] = fma2(x4,  W0[s], a4[r][q]);
                    }
                }
            }
        }
    }

    // ---- epilogue: bias + c0/c4 into slots 0 and 4
    #pragma unroll
    for (int q = 0; q < 4; q++) {
        const int ig = iBase + tx + 16 * q;
        float4 blo = *(const float4*)(bias + (size_t)ig * MV);
        float4 bhi = *(const float4*)(bias + (size_t)ig * MV + 4);
        #pragma unroll
        for (int r = 0; r < 4; r++) {
            float c0e, c0o, c4e, c4o;
            unpack2(a0[r][q], c0e, c0o);
            unpack2(a4[r][q], c4e, c4o);
            const int bE = bBase + 2 * (bp0 + r);

            float4 v0 = blo; v0.x += c0e;
            float4 v1 = bhi; v1.x += c4e;
            float4* o = (float4*)(out + ((size_t)bE * OUT_DIM + ig) * MV);
            o[0] = v0; o[1] = v1;

            v0 = blo; v0.x += c0o;
            v1 = bhi; v1.x += c4o;
            o = (float4*)(out + ((size_t)(bE + 1) * OUT_DIM + ig) * MV);
            o[0] = v0; o[1] = v1;
        }
    }
}

extern "C" void kernel_launch(void* const* d_in, const int* in_sizes, int n_in,
                              void* d_out, int out_size)
{
    const float* x    = (const float*)d_in[0];   // (8192, 256, 8)
    const float* w    = (const float*)d_in[1];   // (256, 256, 8)
    const float* bias = (const float*)d_in[2];   // (256, 8)
    float* out        = (float*)d_out;           // (8192, 256, 8)

    dim3 grid(B_DIM / MT, OUT_DIM / IT);         // (128, 4) = 512 CTAs
    ga_mv_kernel<<<grid, NTHR>>>(x, w, bias, out);
}

// round 7
// speedup vs baseline: 1.5410x; 1.1022x over previous
#include <cuda_runtime.h>
#include <cstdint>

// Problem constants
#define B_DIM   8192
#define IN_DIM  256
#define OUT_DIM 256
#define MV      8

// Tiling: CTA = 64 b (32 bpairs) x 64 i, 128 threads (tx16 x ty8)
// per thread: 4 bpairs x 4 i; double-buffered smem + register prefetch
#define MT      64
#define IT      64
#define KJ      8
#define NCH     (IN_DIM / KJ)   // 32
#define XPAD    36
#define NTHR    128

typedef unsigned long long u64;

__device__ __forceinline__ u64 pack2(float lo, float hi) {
    u64 r; asm("mov.b64 %0, {%1, %2};" : "=l"(r) : "f"(lo), "f"(hi)); return r;
}
__device__ __forceinline__ u64 fma2(u64 a, u64 b, u64 c) {
    u64 d; asm("fma.rn.f32x2 %0, %1, %2, %3;" : "=l"(d) : "l"(a), "l"(b), "l"(c)); return d;
}
__device__ __forceinline__ void unpack2(u64 v, float& lo, float& hi) {
    asm("mov.b64 {%0, %1}, %2;" : "=f"(lo), "=f"(hi) : "l"(v));
}

// y[b,i,0] = bias[i,0] + sum_j x0*w0 + x1*w1 + x2*w2
// y[b,i,4] = bias[i,4] + sum_j x1*w2 - x2*w1 + x4*w0
__global__ void __launch_bounds__(NTHR, 3)
ga_mv_kernel(const float* __restrict__ x,
             const float* __restrict__ w,
             const float* __restrict__ bias,
             float* __restrict__ out)
{
    __shared__ u64 Xs[2][KJ][5][XPAD];   // x0,x1,x2,x4,-x2 as {b even, b odd}
    __shared__ u64 Ws[2][3][KJ][IT];     // w0,w1,w2 duplicated {w,w}

    const int tid   = threadIdx.x;
    const int tx    = tid & 15;        // i = tx + 16q
    const int ty    = tid >> 4;
    const int bp0   = ty * 4;          // 4 bpairs per thread
    const int bBase = blockIdx.x * MT;
    const int iBase = blockIdx.y * IT;

    // staging maps
    const int xj  = tid & 7;           // X: j (cells bp = xbp, xbp+16)
    const int xbp = tid >> 3;
    const int wi  = tid & 63;          // W: i (cells j = wjh + 2t)
    const int wjh = tid >> 6;

    // prefetch registers
    float xA[2][5], xB[2][5];          // {x0,x1,x2,x4} + slot; even/odd rows, 2 cells
    float wv[4][3];

    u64 a0[4][4], a4[4][4];
    #pragma unroll
    for (int r = 0; r < 4; r++)
        #pragma unroll
        for (int q = 0; q < 4; q++) { a0[r][q] = 0ull; a4[r][q] = 0ull; }

    auto LOAD = [&](int c) {
        const int j0 = c * KJ;
        #pragma unroll
        for (int t = 0; t < 2; t++) {
            const int bp = xbp + 16 * t;
            const float* ra = x + ((size_t)(bBase + 2 * bp) * IN_DIM + (j0 + xj)) * MV;
            const float* rb = ra + (size_t)IN_DIM * MV;
            float4 a = *(const float4*)ra;
            xA[t][0] = a.x; xA[t][1] = a.y; xA[t][2] = a.z; xA[t][3] = ra[4];
            float4 b = *(const float4*)rb;
            xB[t][0] = b.x; xB[t][1] = b.y; xB[t][2] = b.z; xB[t][3] = rb[4];
        }
        #pragma unroll
        for (int t = 0; t < 4; t++) {
            const float* wr = w + ((size_t)(j0 + wjh + 2 * t) * OUT_DIM + (iBase + wi)) * MV;
            float4 q = *(const float4*)wr;
            wv[t][0] = q.x; wv[t][1] = q.y; wv[t][2] = q.z;
        }
    };

    auto STORE = [&](int buf) {
        #pragma unroll
        for (int t = 0; t < 2; t++) {
            const int bp = xbp + 16 * t;
            Xs[buf][xj][0][bp] = pack2(xA[t][0],  xB[t][0]);
            Xs[buf][xj][1][bp] = pack2(xA[t][1],  xB[t][1]);
            Xs[buf][xj][2][bp] = pack2(xA[t][2],  xB[t][2]);
            Xs[buf][xj][3][bp] = pack2(xA[t][3],  xB[t][3]);
            Xs[buf][xj][4][bp] = pack2(-xA[t][2], -xB[t][2]);
        }
        #pragma unroll
        for (int t = 0; t < 4; t++) {
            const int jj = wjh + 2 * t;
            Ws[buf][0][jj][wi] = pack2(wv[t][0], wv[t][0]);
            Ws[buf][1][jj][wi] = pack2(wv[t][1], wv[t][1]);
            Ws[buf][2][jj][wi] = pack2(wv[t][2], wv[t][2]);
        }
    };

    LOAD(0);
    STORE(0);
    __syncthreads();

    for (int c = 0; c < NCH; c++) {
        const int buf = c & 1;
        if (c + 1 < NCH) LOAD(c + 1);     // LDG for next chunk, hidden under compute

        #pragma unroll
        for (int j = 0; j < KJ; j++) {
            ulonglong2 v0a = *(const ulonglong2*)&Xs[buf][j][0][bp0];
            ulonglong2 v1a = *(const ulonglong2*)&Xs[buf][j][1][bp0];
            ulonglong2 v2a = *(const ulonglong2*)&Xs[buf][j][2][bp0];
            ulonglong2 v3a = *(const ulonglong2*)&Xs[buf][j][3][bp0];
            ulonglong2 v4a = *(const ulonglong2*)&Xs[buf][j][4][bp0];
            ulonglong2 v0b = *(const ulonglong2*)&Xs[buf][j][0][bp0 + 2];
            ulonglong2 v1b = *(const ulonglong2*)&Xs[buf][j][1][bp0 + 2];
            ulonglong2 v2b = *(const ulonglong2*)&Xs[buf][j][2][bp0 + 2];
            ulonglong2 v3b = *(const ulonglong2*)&Xs[buf][j][3][bp0 + 2];
            ulonglong2 v4b = *(const ulonglong2*)&Xs[buf][j][4][bp0 + 2];

            #pragma unroll
            for (int qh = 0; qh < 2; qh++) {
                u64 W0[2], W1[2], W2[2];
                #pragma unroll
                for (int s = 0; s < 2; s++) {
                    const int q = 2 * qh + s;
                    W0[s] = Ws[buf][0][j][tx + 16 * q];
                    W1[s] = Ws[buf][1][j][tx + 16 * q];
                    W2[s] = Ws[buf][2][j][tx + 16 * q];
                }
                #pragma unroll
                for (int r = 0; r < 4; r++) {
                    const u64 x0  = (r & 2) ? ((r & 1) ? v0b.y : v0b.x) : ((r & 1) ? v0a.y : v0a.x);
                    const u64 x1  = (r & 2) ? ((r & 1) ? v1b.y : v1b.x) : ((r & 1) ? v1a.y : v1a.x);
                    const u64 x2  = (r & 2) ? ((r & 1) ? v2b.y : v2b.x) : ((r & 1) ? v2a.y : v2a.x);
                    const u64 x4  = (r & 2) ? ((r & 1) ? v3b.y : v3b.x) : ((r & 1) ? v3a.y : v3a.x);
                    const u64 x2n = (r & 2) ? ((r & 1) ? v4b.y : v4b.x) : ((r & 1) ? v4a.y : v4a.x);
                    #pragma unroll
                    for (int s = 0; s < 2; s++) {
                        const int q = 2 * qh + s;
                        a0[r][q] = fma2(x0,  W0[s], a0[r][q]);
                        a0[r][q] = fma2(x1,  W1[s], a0[r][q]);
                        a0[r][q] = fma2(x2,  W2[s], a0[r][q]);
                        a4[r][q] = fma2(x1,  W2[s], a4[r][q]);
                        a4[r][q] = fma2(x2n, W1[s], a4[r][q]);
                        a4[r][q] = fma2(x4,  W0[s], a4[r][q]);
                    }
                }
            }
        }

        if (c + 1 < NCH) STORE(buf ^ 1);  // other buffer; consumed last iter
        __syncthreads();
    }

    // ---- epilogue: bias + c0/c4 into slots 0 and 4
    #pragma unroll
    for (int q = 0; q < 4; q++) {
        const int ig = iBase + tx + 16 * q;
        float4 blo = *(const float4*)(bias + (size_t)ig * MV);
        float4 bhi = *(const float4*)(bias + (size_t)ig * MV + 4);
        #pragma unroll
        for (int r = 0; r < 4; r++) {
            float c0e, c0o, c4e, c4o;
            unpack2(a0[r][q], c0e, c0o);
            unpack2(a4[r][q], c4e, c4o);
            const int bE = bBase + 2 * (bp0 + r);

            float4 v0 = blo; v0.x += c0e;
            float4 v1 = bhi; v1.x += c4e;
            float4* o = (float4*)(out + ((size_t)bE * OUT_DIM + ig) * MV);
            o[0] = v0; o[1] = v1;

            v0 = blo; v0.x += c0o;
            v1 = bhi; v1.x += c4o;
            o = (float4*)(out + ((size_t)(bE + 1) * OUT_DIM + ig) * MV);
            o[0] = v0; o[1] = v1;
        }
    }
}

extern "C" void kernel_launch(void* const* d_in, const int* in_sizes, int n_in,
                              void* d_out, int out_size)
{
    const float* x    = (const float*)d_in[0];   // (8192, 256, 8)
    const float* w    = (const float*)d_in[1];   // (256, 256, 8)
    const float* bias = (const float*)d_in[2];   // (256, 8)
    float* out        = (float*)d_out;           // (8192, 256, 8)

    dim3 grid(B_DIM / MT, OUT_DIM / IT);         // (128, 4) = 512 CTAs
    ga_mv_kernel<<<grid, NTHR>>>(x, w, bias, out);
}